// round 5
// baseline (speedup 1.0000x reference)
#include <cuda_runtime.h>
#include <cstdint>

#define B_   128
#define T_   32
#define NS_  200
#define ROWS_TOTAL (B_*NS_)     // 25600
#define HID_ 64
#define G_   256                // 4*HID gates
#define RPB  48                 // rows per block (24 per team)
#define NBLK ((ROWS_TOTAL + RPB - 1)/RPB)   // 534
#define TPB  512                // 2 teams x 256
#define NGRP_T 6                // 4-row groups per team
#define HST  68                 // h row stride (272B, 16B aligned)

// ---------------- scratch ----------------
__device__ float g_xproj[B_*T_*G_];          // 4 MB
__device__ float g_eps[T_*ROWS_TOTAL];       // 3.125 MB

// ---------------- helpers ----------------
__device__ __forceinline__ uint32_t rotl32(uint32_t x, int d){ return (x<<d)|(x>>(32-d)); }
__device__ __forceinline__ float sigmoidf_(float x){ return 1.0f/(1.0f+expf(-x)); }
__device__ __forceinline__ float softplusf_(float x){ return fmaxf(x,0.0f) + log1pf(expf(-fabsf(x))); }

__device__ __forceinline__ uint64_t pack2(float a, float b){
  uint64_t r; asm("mov.b64 %0, {%1,%2};" : "=l"(r) : "f"(a), "f"(b)); return r;
}
__device__ __forceinline__ float hsum2(uint64_t v){
  float a,b; asm("mov.b64 {%0,%1}, %2;" : "=f"(a), "=f"(b) : "l"(v)); return a+b;
}
#define FMA2(acc, w, h) asm("fma.rn.f32x2 %0, %1, %2, %3;" : "=l"(acc) : "l"(w), "l"(h), "l"(acc))

// XLA f32 ErfInv (Giles)
__device__ __forceinline__ float erfinv_xla(float x){
  float w = -log1pf(-x*x);
  float p;
  if (w < 5.0f) {
    w = w - 2.5f;
    p = 2.81022636e-08f;
    p = fmaf(p, w, 3.43273939e-07f);
    p = fmaf(p, w, -3.5233877e-06f);
    p = fmaf(p, w, -4.39150654e-06f);
    p = fmaf(p, w, 0.00021858087f);
    p = fmaf(p, w, -0.00125372503f);
    p = fmaf(p, w, -0.00417768164f);
    p = fmaf(p, w, 0.246640727f);
    p = fmaf(p, w, 1.50140941f);
  } else {
    w = sqrtf(w) - 3.0f;
    p = -0.000200214257f;
    p = fmaf(p, w, 0.000100950558f);
    p = fmaf(p, w, 0.00134934322f);
    p = fmaf(p, w, -0.00367342844f);
    p = fmaf(p, w, 0.00573950773f);
    p = fmaf(p, w, -0.0076224613f);
    p = fmaf(p, w, 0.00943887047f);
    p = fmaf(p, w, 1.00167406f);
    p = fmaf(p, w, 2.83297682f);
  }
  return p * x;
}

__device__ __forceinline__ float bits_to_normal(uint32_t bits){
  float u = __uint_as_float((bits>>9) | 0x3f800000u) - 1.0f;
  float x = fmaf(u, 2.0f, -0.99999994f);
  x = fmaxf(-0.99999994f, x);
  return 1.41421356f * erfinv_xla(x);
}

// ---------------- eps: partitionable Threefry, bits1^bits2 ----------------
__global__ void eps_kernel(){
  const uint32_t N = (uint32_t)(T_*ROWS_TOTAL);
  uint32_t j = blockIdx.x*blockDim.x + threadIdx.x;
  if (j >= N) return;
  const uint32_t ks0 = 0u, ks1 = 42u, ks2 = 0x1BD11BDAu ^ 42u;
  uint32_t x0 = 0u, x1 = j;
  x0 += ks0; x1 += ks1;
#define RND_(r) { x0 += x1; x1 = rotl32(x1, (r)); x1 ^= x0; }
  RND_(13) RND_(15) RND_(26) RND_(6)   x0 += ks1; x1 += ks2 + 1u;
  RND_(17) RND_(29) RND_(16) RND_(24)  x0 += ks2; x1 += ks0 + 2u;
  RND_(13) RND_(15) RND_(26) RND_(6)   x0 += ks0; x1 += ks1 + 3u;
  RND_(17) RND_(29) RND_(16) RND_(24)  x0 += ks1; x1 += ks2 + 4u;
  RND_(13) RND_(15) RND_(26) RND_(6)   x0 += ks2; x1 += ks0 + 5u;
#undef RND_
  g_eps[j] = bits_to_normal(x0 ^ x1);
}

// ---------------- xproj ----------------
__global__ void xproj_kernel(const float* __restrict__ dec_cont,
                             const float* __restrict__ emb0,
                             const float* __restrict__ emb1,
                             const float* __restrict__ Wih0,
                             const float* __restrict__ bih0,
                             const float* __restrict__ bhh0,
                             const int*   __restrict__ dec_cat){
  int bt = blockIdx.x;
  int g  = threadIdx.x;
  __shared__ float feat[32];
  if (g < 32) {
    float v = 0.0f;
    if (g >= 1 && g < 6) {
      v = dec_cont[bt*6 + g];
    } else if (g >= 6 && g < 16) {
      int c0 = dec_cat[bt*2 + 0];
      v = emb0[c0*10 + (g-6)];
    } else if (g >= 16) {
      int c1 = dec_cat[bt*2 + 1];
      v = emb1[c1*16 + (g-16)];
    }
    feat[g] = v;
  }
  __syncthreads();
  float acc = bih0[g] + bhh0[g];
  #pragma unroll
  for (int k = 1; k < 32; k++) acc = fmaf(Wih0[g*32 + k], feat[k], acc);
  g_xproj[bt*G_ + g] = acc;
}

// ---------------- main persistent LSTM kernel ----------------
__global__ __launch_bounds__(TPB, 1)
void deepar_kernel(const float* __restrict__ ts,
                   const float* __restrict__ one_off,
                   const float* __restrict__ Wih0,
                   const float* __restrict__ Whh0,
                   const float* __restrict__ Wih1,
                   const float* __restrict__ Whh1,
                   const float* __restrict__ bih1,
                   const float* __restrict__ bhh1,
                   const float* __restrict__ Wproj,
                   const float* __restrict__ bproj,
                   const float* __restrict__ h0in,
                   const float* __restrict__ c0in,
                   float* __restrict__ out)
{
  extern __shared__ float sm[];
  float* sWhh0 = sm;                   // [16][256*4] chunk-major: c*1024 + 4*g
  float* sWih1 = sm + 16384;
  float* sWhh1 = sm + 32768;
  float* sH0   = sm + 49152;           // [2*4][HST]
  float* sH1   = sH0 + 8*HST;          // [2*4][HST]
  float* sG    = sH1 + 8*HST;          // [2][4][256]
  float* sRed  = sG + 2048;            // [2][4][2][2]
  float* sLagS = sRed + 32;            // [2][4]
  // total floats = 49152 + 544 + 544 + 2048 + 32 + 8 = 52328 (209312 B)

  const int tid  = threadIdx.x;
  const int team = tid >> 8;
  const int tt   = tid & 255;
  const int g    = tt;
  const int sr   = tt >> 6, ch = tt & 63;
  const int row0 = blockIdx.x * RPB;

  // --- weights: chunk-major float4 copy (LDS.128-friendly, conflict-free) ---
  if (team == 0) {
    #pragma unroll
    for (int c = 0; c < 16; c++) {
      *(float4*)&sWhh0[c*1024 + 4*g] = *(const float4*)&Whh0[g*64 + 4*c];
      *(float4*)&sWih1[c*1024 + 4*g] = *(const float4*)&Wih1[g*64 + 4*c];
    }
  } else {
    #pragma unroll
    for (int c = 0; c < 16; c++)
      *(float4*)&sWhh1[c*1024 + 4*g] = *(const float4*)&Whh1[g*64 + 4*c];
  }
  const float w0c = Wih0[g*32];           // column 0 of layer0 input weights
  const float bl1 = bih1[g] + bhh1[g];
  const float wp0 = Wproj[ch], wp1 = Wproj[64 + ch];
  const float bp0 = bproj[0],  bp1 = bproj[1];
  __syncthreads();

#define TBAR() asm volatile("bar.sync %0, 256;" :: "r"(team+1) : "memory")

  float* sGt = sG + team*1024;
  float* hb0 = sH0 + team*4*HST;
  float* hb1 = sH1 + team*4*HST;
  float* red = sRed + team*16;
  float* lag = sLagS + team*4;

  #pragma unroll 1
  for (int gi = 0; gi < NGRP_T; gi++) {
    const int gr0 = row0 + team*24 + gi*4;
    const int myrow = gr0 + sr;
    const bool valid = myrow < ROWS_TOTAL;
    const int mb = (valid ? myrow : ROWS_TOTAL-1) / NS_;

    // per-group state init
    float c0v = valid ? c0in[mb*HID_ + ch] : 0.f;
    float c1v = valid ? c0in[B_*HID_ + mb*HID_ + ch] : 0.f;
    hb0[sr*HST + ch] = valid ? h0in[mb*HID_ + ch] : 0.f;
    hb1[sr*HST + ch] = valid ? h0in[B_*HID_ + mb*HID_ + ch] : 0.f;
    if (tt < 4) {
      int r = gr0 + tt; bool v = r < ROWS_TOTAL;
      int b = (v ? r : ROWS_TOTAL-1)/NS_;
      lag[tt] = v ? one_off[b] : 0.f;
    }
    const float cen = valid ? ts[2*mb]   : 0.f;
    const float scl = valid ? ts[2*mb+1] : 1.f;

    // xproj row pointers (+ first-t prefetch)
    const int q0 = min(gr0+0, ROWS_TOTAL-1)/NS_;
    const int q1 = min(gr0+1, ROWS_TOTAL-1)/NS_;
    const int q2 = min(gr0+2, ROWS_TOTAL-1)/NS_;
    const int q3 = min(gr0+3, ROWS_TOTAL-1)/NS_;
    const float* xpp0 = g_xproj + q0*T_*G_ + g;
    const float* xpp1 = g_xproj + q1*T_*G_ + g;
    const float* xpp2 = g_xproj + q2*T_*G_ + g;
    const float* xpp3 = g_xproj + q3*T_*G_ + g;
    float xq0 = xpp0[0], xq1 = xpp1[0], xq2 = xpp2[0], xq3 = xpp3[0];

    const int egr = valid ? myrow : 0;
    float ecur = 0.f;
    if (ch == 0) ecur = g_eps[egr];     // eps(t=0)
    TBAR();

    #pragma unroll 1
    for (int t = 0; t < T_; t++) {
      const int tn = (t+1 < T_) ? t+1 : t;
      // ---- layer0 gates: xproj + w0c*lag + Whh0 @ h0 ----
      uint64_t a0 = pack2(fmaf(w0c, lag[0], xq0), 0.f);
      uint64_t a1 = pack2(fmaf(w0c, lag[1], xq1), 0.f);
      uint64_t a2 = pack2(fmaf(w0c, lag[2], xq2), 0.f);
      uint64_t a3 = pack2(fmaf(w0c, lag[3], xq3), 0.f);
      // prefetch next-t xproj (off critical path)
      xq0 = xpp0[tn*G_]; xq1 = xpp1[tn*G_]; xq2 = xpp2[tn*G_]; xq3 = xpp3[tn*G_];
      #pragma unroll
      for (int c = 0; c < 16; c++) {
        ulonglong2 w  = *(const ulonglong2*)&sWhh0[c*1024 + 4*g];
        ulonglong2 hA = *(const ulonglong2*)&hb0[0*HST + 4*c];
        ulonglong2 hB = *(const ulonglong2*)&hb0[1*HST + 4*c];
        ulonglong2 hC = *(const ulonglong2*)&hb0[2*HST + 4*c];
        ulonglong2 hD = *(const ulonglong2*)&hb0[3*HST + 4*c];
        FMA2(a0, w.x, hA.x); FMA2(a0, w.y, hA.y);
        FMA2(a1, w.x, hB.x); FMA2(a1, w.y, hB.y);
        FMA2(a2, w.x, hC.x); FMA2(a2, w.y, hC.y);
        FMA2(a3, w.x, hD.x); FMA2(a3, w.y, hD.y);
      }
      sGt[      g] = hsum2(a0);
      sGt[256 + g] = hsum2(a1);
      sGt[512 + g] = hsum2(a2);
      sGt[768 + g] = hsum2(a3);
      TBAR();
      // ---- h0/c0 update ----
      {
        float xi = sGt[sr*256 +       ch];
        float xf = sGt[sr*256 +  64 + ch];
        float xg = sGt[sr*256 + 128 + ch];
        float xo = sGt[sr*256 + 192 + ch];
        c0v = sigmoidf_(xf)*c0v + sigmoidf_(xi)*tanhf(xg);
        hb0[sr*HST + ch] = sigmoidf_(xo)*tanhf(c0v);
      }
      TBAR();
      // ---- layer1 gates: b1 + Wih1 @ h0_new + Whh1 @ h1 ----
      a0 = pack2(bl1, 0.f); a1 = a0; a2 = a0; a3 = a0;
      #pragma unroll
      for (int c = 0; c < 16; c++) {
        ulonglong2 wI = *(const ulonglong2*)&sWih1[c*1024 + 4*g];
        ulonglong2 wH = *(const ulonglong2*)&sWhh1[c*1024 + 4*g];
        ulonglong2 hA = *(const ulonglong2*)&hb0[0*HST + 4*c];
        ulonglong2 hB = *(const ulonglong2*)&hb0[1*HST + 4*c];
        ulonglong2 hC = *(const ulonglong2*)&hb0[2*HST + 4*c];
        ulonglong2 hD = *(const ulonglong2*)&hb0[3*HST + 4*c];
        FMA2(a0, wI.x, hA.x); FMA2(a0, wI.y, hA.y);
        FMA2(a1, wI.x, hB.x); FMA2(a1, wI.y, hB.y);
        FMA2(a2, wI.x, hC.x); FMA2(a2, wI.y, hC.y);
        FMA2(a3, wI.x, hD.x); FMA2(a3, wI.y, hD.y);
        ulonglong2 jA = *(const ulonglong2*)&hb1[0*HST + 4*c];
        ulonglong2 jB = *(const ulonglong2*)&hb1[1*HST + 4*c];
        ulonglong2 jC = *(const ulonglong2*)&hb1[2*HST + 4*c];
        ulonglong2 jD = *(const ulonglong2*)&hb1[3*HST + 4*c];
        FMA2(a0, wH.x, jA.x); FMA2(a0, wH.y, jA.y);
        FMA2(a1, wH.x, jB.x); FMA2(a1, wH.y, jB.y);
        FMA2(a2, wH.x, jC.x); FMA2(a2, wH.y, jC.y);
        FMA2(a3, wH.x, jD.x); FMA2(a3, wH.y, jD.y);
      }
      sGt[      g] = hsum2(a0);
      sGt[256 + g] = hsum2(a1);
      sGt[512 + g] = hsum2(a2);
      sGt[768 + g] = hsum2(a3);
      TBAR();
      // ---- h1/c1 update + fused projection partials ----
      float h1v;
      {
        float xi = sGt[sr*256 +       ch];
        float xf = sGt[sr*256 +  64 + ch];
        float xg = sGt[sr*256 + 128 + ch];
        float xo = sGt[sr*256 + 192 + ch];
        c1v = sigmoidf_(xf)*c1v + sigmoidf_(xi)*tanhf(xg);
        h1v = sigmoidf_(xo)*tanhf(c1v);
        hb1[sr*HST + ch] = h1v;
      }
      float p0 = wp0*h1v, p1 = wp1*h1v;
      #pragma unroll
      for (int off = 16; off; off >>= 1) {
        p0 += __shfl_xor_sync(0xffffffffu, p0, off);
        p1 += __shfl_xor_sync(0xffffffffu, p1, off);
      }
      if ((tt & 31) == 0) {
        int half = (tt >> 5) & 1;
        red[sr*4 + half*2 + 0] = p0;
        red[sr*4 + half*2 + 1] = p1;
      }
      TBAR();
      // ---- combine + sample (one thread per row: ch==0) ----
      if (ch == 0) {
        float r0 = red[sr*4 + 0] + red[sr*4 + 2] + bp0;
        float r1 = red[sr*4 + 1] + red[sr*4 + 3] + bp1;
        float loc  = fmaf(r0, scl, cen);
        float sig  = softplusf_(r1) * scl;
        float pred = fmaf(sig, ecur, loc);
        if (valid) {
          int s = myrow - mb*NS_;
          out[(mb*T_ + t)*NS_ + s] = pred;
        }
        lag[sr] = (pred - cen) / scl;
        ecur = g_eps[tn*ROWS_TOTAL + egr];   // prefetch eps(t+1)
      }
      TBAR();
    }
  }
#undef TBAR
}

// ---------------- launch ----------------
extern "C" void kernel_launch(void* const* d_in, const int* in_sizes, int n_in,
                              void* d_out, int out_size) {
  (void)in_sizes; (void)n_in; (void)out_size;
  const float* dec_cont = (const float*)d_in[0];
  const float* one_off  = (const float*)d_in[1];
  const float* ts       = (const float*)d_in[2];
  const float* emb0     = (const float*)d_in[3];
  const float* emb1     = (const float*)d_in[4];
  const float* Wih0     = (const float*)d_in[5];
  const float* Whh0     = (const float*)d_in[6];
  const float* bih0     = (const float*)d_in[7];
  const float* bhh0     = (const float*)d_in[8];
  const float* Wih1     = (const float*)d_in[9];
  const float* Whh1     = (const float*)d_in[10];
  const float* bih1     = (const float*)d_in[11];
  const float* bhh1     = (const float*)d_in[12];
  const float* Wproj    = (const float*)d_in[13];
  const float* bproj    = (const float*)d_in[14];
  const float* h0in     = (const float*)d_in[15];
  const float* c0in     = (const float*)d_in[16];
  const int*   dec_cat  = (const int*)d_in[17];
  float* out = (float*)d_out;

  const size_t SMEM_BYTES = (size_t)(49152 + 2*8*HST + 2048 + 32 + 8) * sizeof(float);

  eps_kernel<<<(T_*ROWS_TOTAL + 255)/256, 256>>>();
  xproj_kernel<<<B_*T_, 256>>>(dec_cont, emb0, emb1, Wih0, bih0, bhh0, dec_cat);

  cudaFuncSetAttribute(deepar_kernel, cudaFuncAttributeMaxDynamicSharedMemorySize, (int)SMEM_BYTES);
  deepar_kernel<<<NBLK, TPB, SMEM_BYTES>>>(ts, one_off, Wih0, Whh0, Wih1, Whh1,
                                           bih1, bhh1, Wproj, bproj, h0in, c0in, out);
}

// round 9
// speedup vs baseline: 6.2444x; 6.2444x over previous
#include <cuda_runtime.h>
#include <cuda_fp16.h>
#include <cstdint>

#define B_ 128
#define T_ 32
#define NS_ 200
#define ROWS_TOTAL 25600
#define G_ 256
#define RPC 64
#define NCTA 400
#define TPB 256
#define GS 261
#define HS 36
#define OF_GATE 0
#define OF_H0 16704
#define OF_H1 19008
#define OF_XG 21312
#define OF_W0C 22336
#define OF_BL1 22592
#define OF_WP 22848
#define OF_LAG 22976
#define OF_RED 23040
#define SM_WORDS 23552

__device__ float g_xproj[B_*T_*G_];
__device__ float g_eps[T_*ROWS_TOTAL];

__device__ __forceinline__ uint32_t rotl32(uint32_t x,int d){return (x<<d)|(x>>(32-d));}
__device__ __forceinline__ float sigf(float x){return __fdividef(1.0f,1.0f+__expf(-x));}
__device__ __forceinline__ float tanhf_(float x){return 1.0f-__fdividef(2.0f,1.0f+__expf(2.0f*x));}
__device__ __forceinline__ float softplusf_(float x){return fmaxf(x,0.0f)+log1pf(expf(-fabsf(x)));}

__device__ __forceinline__ float erfinv_xla(float x){
  float w=-log1pf(-x*x),p;
  if(w<5.0f){w=w-2.5f;
    p=2.81022636e-08f;p=fmaf(p,w,3.43273939e-07f);p=fmaf(p,w,-3.5233877e-06f);
    p=fmaf(p,w,-4.39150654e-06f);p=fmaf(p,w,0.00021858087f);p=fmaf(p,w,-0.00125372503f);
    p=fmaf(p,w,-0.00417768164f);p=fmaf(p,w,0.246640727f);p=fmaf(p,w,1.50140941f);
  }else{w=sqrtf(w)-3.0f;
    p=-0.000200214257f;p=fmaf(p,w,0.000100950558f);p=fmaf(p,w,0.00134934322f);
    p=fmaf(p,w,-0.00367342844f);p=fmaf(p,w,0.00573950773f);p=fmaf(p,w,-0.0076224613f);
    p=fmaf(p,w,0.00943887047f);p=fmaf(p,w,1.00167406f);p=fmaf(p,w,2.83297682f);}
  return p*x;
}
__device__ __forceinline__ float bits_to_normal(uint32_t bits){
  float u=__uint_as_float((bits>>9)|0x3f800000u)-1.0f;
  float x=fmaf(u,2.0f,-0.99999994f);
  x=fmaxf(-0.99999994f,x);
  return 1.41421356f*erfinv_xla(x);
}

__global__ void setup_kernel(const float* __restrict__ dec_cont,const float* __restrict__ emb0,
    const float* __restrict__ emb1,const float* __restrict__ Wih0,const float* __restrict__ bih0,
    const float* __restrict__ bhh0,const int* __restrict__ dec_cat){
  if(blockIdx.x>=4096){
    uint32_t j=(blockIdx.x-4096)*blockDim.x+threadIdx.x;
    if(j>=(uint32_t)(T_*ROWS_TOTAL))return;
    const uint32_t ks0=0u,ks1=42u,ks2=0x1BD11BDAu^42u;
    uint32_t x0=0u,x1=j;
    x0+=ks0;x1+=ks1;
#define RND_(r){x0+=x1;x1=rotl32(x1,(r));x1^=x0;}
    RND_(13)RND_(15)RND_(26)RND_(6)  x0+=ks1;x1+=ks2+1u;
    RND_(17)RND_(29)RND_(16)RND_(24) x0+=ks2;x1+=ks0+2u;
    RND_(13)RND_(15)RND_(26)RND_(6)  x0+=ks0;x1+=ks1+3u;
    RND_(17)RND_(29)RND_(16)RND_(24) x0+=ks1;x1+=ks2+4u;
    RND_(13)RND_(15)RND_(26)RND_(6)  x0+=ks2;x1+=ks0+5u;
#undef RND_
    g_eps[j]=bits_to_normal(x0^x1);
    return;
  }
  int bt=blockIdx.x,g=threadIdx.x;
  __shared__ float feat[32];
  if(g<32){
    float v=0.0f;
    if(g>=1&&g<6)v=dec_cont[bt*6+g];
    else if(g>=6&&g<16)v=emb0[dec_cat[bt*2]*10+(g-6)];
    else if(g>=16)v=emb1[dec_cat[bt*2+1]*16+(g-16)];
    feat[g]=v;
  }
  __syncthreads();
  float acc=bih0[g]+bhh0[g];
  #pragma unroll
  for(int k=1;k<32;k++)acc=fmaf(Wih0[g*32+k],feat[k],acc);
  g_xproj[bt*G_+g]=acc;
}

#define MMA(d,a,bb0,bb1) \
  asm volatile("mma.sync.aligned.m16n8k16.row.col.f32.f16.f16.f32 " \
    "{%0,%1,%2,%3}, {%4,%5,%6,%7}, {%8,%9}, {%0,%1,%2,%3};" \
    : "+f"((d)[0]),"+f"((d)[1]),"+f"((d)[2]),"+f"((d)[3]) \
    : "r"((a)[0]),"r"((a)[1]),"r"((a)[2]),"r"((a)[3]),"r"(bb0),"r"(bb1))

__device__ __forceinline__ uint32_t f2h2(float lo,float hi){
  __half2 h=__floats2half2_rn(lo,hi);
  return *reinterpret_cast<uint32_t*>(&h);
}

__global__ __launch_bounds__(TPB,1)
void deepar_mma(const float* __restrict__ ts,const float* __restrict__ one_off,
    const float* __restrict__ Wih0,const float* __restrict__ Whh0,
    const float* __restrict__ Wih1,const float* __restrict__ Whh1,
    const float* __restrict__ bih1,const float* __restrict__ bhh1,
    const float* __restrict__ Wproj,const float* __restrict__ bproj,
    const float* __restrict__ h0in,const float* __restrict__ c0in,
    float* __restrict__ out)
{
  extern __shared__ float sm[];
  uint32_t* smu=(uint32_t*)sm;
  const int tid=threadIdx.x;
  const int w=tid>>5,lane=tid&31;
  const int la=lane>>2,lb=lane&3;
  const int gr0=blockIdx.x*RPC;
  const int b0=gr0/NS_,bL=(gr0+RPC-1)/NS_;
  const int r=tid&63,cb=tid>>6,ch0=cb*16;
  const int myb=(gr0+r)/NS_;
  const int bsel=(myb!=b0)?1:0;

  uint32_t aW0[2][4][4],aI1[2][4][4],aH1[2][4][4];
  #pragma unroll
  for(int mt=0;mt<2;mt++){
    #pragma unroll
    for(int kt=0;kt<4;kt++){
      int m=w*32+mt*16+la,k=kt*16+lb*2;
      aW0[mt][kt][0]=f2h2(Whh0[m*64+k],Whh0[m*64+k+1]);
      aW0[mt][kt][1]=f2h2(Whh0[(m+8)*64+k],Whh0[(m+8)*64+k+1]);
      aW0[mt][kt][2]=f2h2(Whh0[m*64+k+8],Whh0[m*64+k+9]);
      aW0[mt][kt][3]=f2h2(Whh0[(m+8)*64+k+8],Whh0[(m+8)*64+k+9]);
      aI1[mt][kt][0]=f2h2(Wih1[m*64+k],Wih1[m*64+k+1]);
      aI1[mt][kt][1]=f2h2(Wih1[(m+8)*64+k],Wih1[(m+8)*64+k+1]);
      aI1[mt][kt][2]=f2h2(Wih1[m*64+k+8],Wih1[m*64+k+9]);
      aI1[mt][kt][3]=f2h2(Wih1[(m+8)*64+k+8],Wih1[(m+8)*64+k+9]);
      aH1[mt][kt][0]=f2h2(Whh1[m*64+k],Whh1[m*64+k+1]);
      aH1[mt][kt][1]=f2h2(Whh1[(m+8)*64+k],Whh1[(m+8)*64+k+1]);
      aH1[mt][kt][2]=f2h2(Whh1[m*64+k+8],Whh1[m*64+k+9]);
      aH1[mt][kt][3]=f2h2(Whh1[(m+8)*64+k+8],Whh1[(m+8)*64+k+9]);
    }
  }

  sm[OF_W0C+tid]=Wih0[tid*32];
  sm[OF_BL1+tid]=bih1[tid]+bhh1[tid];
  if(tid<128)sm[OF_WP+tid]=Wproj[tid];
  if(tid<64)sm[OF_LAG+tid]=one_off[(gr0+tid)/NS_];
  for(int q=tid;q<512;q+=TPB){
    int sel=q>>8,g=q&255;
    sm[OF_XG+sel*256+g]=g_xproj[((sel?bL:b0)*T_)*G_+g];
  }
  float c0v[16],c1v[16];
  {
    #pragma unroll
    for(int j=0;j<16;j++){
      int ch=ch0+j;
      c0v[j]=c0in[myb*64+ch];
      c1v[j]=c0in[8192+myb*64+ch];
    }
    __half2* h0p=(__half2*)&smu[OF_H0+r*HS+(ch0>>1)];
    __half2* h1p=(__half2*)&smu[OF_H1+r*HS+(ch0>>1)];
    #pragma unroll
    for(int j=0;j<8;j++){
      int ch=ch0+2*j;
      h0p[j]=__floats2half2_rn(h0in[myb*64+ch],h0in[myb*64+ch+1]);
      h1p[j]=__floats2half2_rn(h0in[8192+myb*64+ch],h0in[8192+myb*64+ch+1]);
    }
  }
  float cen=0.f,scl=1.f,bp0=0.f,bp1=0.f;
  int sb=0,ss=0;
  if(tid<64){
    int sgr=gr0+tid;
    sb=sgr/NS_;ss=sgr-sb*NS_;
    cen=ts[2*sb];scl=ts[2*sb+1];
    bp0=bproj[0];bp1=bproj[1];
  }
  __syncthreads();

  #pragma unroll 1
  for(int t=0;t<T_;t++){
    // phase 1: L0 MMA (+ finalize sample t-1 on tid<64)
    #pragma unroll
    for(int nt=0;nt<8;nt++){
      float d0[4]={0,0,0,0},d1[4]={0,0,0,0};
      #pragma unroll
      for(int kt=0;kt<4;kt++){
        uint32_t b0r=smu[OF_H0+(nt*8+la)*HS+kt*8+lb];
        uint32_t b1r=smu[OF_H0+(nt*8+la)*HS+kt*8+lb+4];
        MMA(d0,aW0[0][kt],b0r,b1r);
        MMA(d1,aW0[1][kt],b0r,b1r);
      }
      int n0=nt*8+lb*2,m=w*32+la;
      sm[OF_GATE+n0*GS+m]=d0[0];      sm[OF_GATE+(n0+1)*GS+m]=d0[1];
      sm[OF_GATE+n0*GS+m+8]=d0[2];    sm[OF_GATE+(n0+1)*GS+m+8]=d0[3];
      sm[OF_GATE+n0*GS+m+16]=d1[0];   sm[OF_GATE+(n0+1)*GS+m+16]=d1[1];
      sm[OF_GATE+n0*GS+m+24]=d1[2];   sm[OF_GATE+(n0+1)*GS+m+24]=d1[3];
    }
    if(t>0&&tid<64){
      int tp=t-1;
      float r0=sm[OF_RED+tid]+sm[OF_RED+64+tid]+sm[OF_RED+128+tid]+sm[OF_RED+192+tid]+bp0;
      float r1=sm[OF_RED+256+tid]+sm[OF_RED+320+tid]+sm[OF_RED+384+tid]+sm[OF_RED+448+tid]+bp1;
      float loc=fmaf(r0,scl,cen);
      float sig=softplusf_(r1)*scl;
      float pred=fmaf(sig,g_eps[tp*ROWS_TOTAL+gr0+tid],loc);
      out[(sb*T_+tp)*NS_+ss]=pred;
      sm[OF_LAG+tid]=(pred-cen)/scl;
    }
    __syncthreads();
    // phase 2: L0 update
    {
      const float lagv=sm[OF_LAG+r];
      const float* xg=&sm[OF_XG+((t&1)*2+bsel)*256];
      const float* gp=&sm[OF_GATE+r*GS];
      float hn[16];
      #pragma unroll
      for(int j=0;j<16;j++){
        int ch=ch0+j;
        float gi=gp[ch]     +fmaf(sm[OF_W0C+ch],lagv,xg[ch]);
        float gf=gp[64+ch]  +fmaf(sm[OF_W0C+64+ch],lagv,xg[64+ch]);
        float gg=gp[128+ch] +fmaf(sm[OF_W0C+128+ch],lagv,xg[128+ch]);
        float go=gp[192+ch] +fmaf(sm[OF_W0C+192+ch],lagv,xg[192+ch]);
        float c=sigf(gf)*c0v[j]+sigf(gi)*tanhf_(gg);
        c0v[j]=c;
        hn[j]=sigf(go)*tanhf_(c);
      }
      __half2* h0p=(__half2*)&smu[OF_H0+r*HS+(ch0>>1)];
      #pragma unroll
      for(int j=0;j<8;j++)h0p[j]=__floats2half2_rn(hn[2*j],hn[2*j+1]);
    }
    __syncthreads();
    // phase 3: L1 MMA
    #pragma unroll
    for(int nt=0;nt<8;nt++){
      float d0[4]={0,0,0,0},d1[4]={0,0,0,0};
      #pragma unroll
      for(int kt=0;kt<4;kt++){
        uint32_t b0r=smu[OF_H0+(nt*8+la)*HS+kt*8+lb];
        uint32_t b1r=smu[OF_H0+(nt*8+la)*HS+kt*8+lb+4];
        MMA(d0,aI1[0][kt],b0r,b1r);
        MMA(d1,aI1[1][kt],b0r,b1r);
      }
      #pragma unroll
      for(int kt=0;kt<4;kt++){
        uint32_t b0r=smu[OF_H1+(nt*8+la)*HS+kt*8+lb];
        uint32_t b1r=smu[OF_H1+(nt*8+la)*HS+kt*8+lb+4];
        MMA(d0,aH1[0][kt],b0r,b1r);
        MMA(d1,aH1[1][kt],b0r,b1r);
      }
      int n0=nt*8+lb*2,m=w*32+la;
      sm[OF_GATE+n0*GS+m]=d0[0];      sm[OF_GATE+(n0+1)*GS+m]=d0[1];
      sm[OF_GATE+n0*GS+m+8]=d0[2];    sm[OF_GATE+(n0+1)*GS+m+8]=d0[3];
      sm[OF_GATE+n0*GS+m+16]=d1[0];   sm[OF_GATE+(n0+1)*GS+m+16]=d1[1];
      sm[OF_GATE+n0*GS+m+24]=d1[2];   sm[OF_GATE+(n0+1)*GS+m+24]=d1[3];
    }
    __syncthreads();
    // phase 4: L1 update + projection partials + stage xproj t+1
    {
      const float* gp=&sm[OF_GATE+r*GS];
      float hn[16],p0=0.f,p1=0.f;
      #pragma unroll
      for(int j=0;j<16;j++){
        int ch=ch0+j;
        float gi=gp[ch]+sm[OF_BL1+ch];
        float gf=gp[64+ch]+sm[OF_BL1+64+ch];
        float gg=gp[128+ch]+sm[OF_BL1+128+ch];
        float go=gp[192+ch]+sm[OF_BL1+192+ch];
        float c=sigf(gf)*c1v[j]+sigf(gi)*tanhf_(gg);
        c1v[j]=c;
        float h=sigf(go)*tanhf_(c);
        hn[j]=h;
        p0=fmaf(sm[OF_WP+ch],h,p0);
        p1=fmaf(sm[OF_WP+64+ch],h,p1);
      }
      __half2* h1p=(__half2*)&smu[OF_H1+r*HS+(ch0>>1)];
      #pragma unroll
      for(int j=0;j<8;j++)h1p[j]=__floats2half2_rn(hn[2*j],hn[2*j+1]);
      sm[OF_RED+tid]=p0;
      sm[OF_RED+256+tid]=p1;
    }
    if(t+1<T_){
      for(int q=tid;q<512;q+=TPB){
        int sel=q>>8,g=q&255;
        sm[OF_XG+(((t+1)&1)*2+sel)*256+g]=g_xproj[((sel?bL:b0)*T_+t+1)*G_+g];
      }
    }
    __syncthreads();
  }
  if(tid<64){
    float r0=sm[OF_RED+tid]+sm[OF_RED+64+tid]+sm[OF_RED+128+tid]+sm[OF_RED+192+tid]+bp0;
    float r1=sm[OF_RED+256+tid]+sm[OF_RED+320+tid]+sm[OF_RED+384+tid]+sm[OF_RED+448+tid]+bp1;
    float loc=fmaf(r0,scl,cen);
    float sig=softplusf_(r1)*scl;
    float pred=fmaf(sig,g_eps[(T_-1)*ROWS_TOTAL+gr0+tid],loc);
    out[(sb*T_+(T_-1))*NS_+ss]=pred;
  }
}

extern "C" void kernel_launch(void* const* d_in,const int* in_sizes,int n_in,
                              void* d_out,int out_size){
  (void)in_sizes;(void)n_in;(void)out_size;
  const float* dec_cont=(const float*)d_in[0];
  const float* one_off =(const float*)d_in[1];
  const float* ts      =(const float*)d_in[2];
  const float* emb0    =(const float*)d_in[3];
  const float* emb1    =(const float*)d_in[4];
  const float* Wih0    =(const float*)d_in[5];
  const float* Whh0    =(const float*)d_in[6];
  const float* bih0    =(const float*)d_in[7];
  const float* bhh0    =(const float*)d_in[8];
  const float* Wih1    =(const float*)d_in[9];
  const float* Whh1    =(const float*)d_in[10];
  const float* bih1    =(const float*)d_in[11];
  const float* bhh1    =(const float*)d_in[12];
  const float* Wproj   =(const float*)d_in[13];
  const float* bproj   =(const float*)d_in[14];
  const float* h0in    =(const float*)d_in[15];
  const float* c0in    =(const float*)d_in[16];
  const int*   dec_cat =(const int*)d_in[17];
  float* out=(float*)d_out;

  setup_kernel<<<4096+(T_*ROWS_TOTAL+255)/256,256>>>(dec_cont,emb0,emb1,Wih0,bih0,bhh0,dec_cat);

  cudaFuncSetAttribute(deepar_mma,cudaFuncAttributeMaxDynamicSharedMemorySize,SM_WORDS*4);
  deepar_mma<<<NCTA,TPB,SM_WORDS*4>>>(ts,one_off,Wih0,Whh0,Wih1,Whh1,
                                      bih1,bhh1,Wproj,bproj,h0in,c0in,out);
}